// round 6
// baseline (speedup 1.0000x reference)
#include <cuda_runtime.h>
#include <cstdint>
#include <cstddef>

// ============================================================================
// out[8192,4096] = x[8192,4096] @ sym12x12(W)[4096,4096]^T + bias
// Base-sm_103 feature set only (no tcgen05 / clusters): classic warp-level
// mma.sync tf32 GEMM with cp.async 5-stage pipeline + ldmatrix operand fetch.
// Prep kernels: (1) symmetrize W by 12x12 blocks + RNA-round to tf32,
//               (2) RNA-round x to tf32.  fp32 accumulation.
// ============================================================================

#define M_DIM 8192
#define N_DIM 4096
#define K_DIM 4096

#define CTA_M 128
#define CTA_N 128
#define CTA_K 32
#define STAGES 5
#define THREADS 256
#define NK_ITERS (K_DIM / CTA_K)          // 128

#define TILE_ROW_BYTES 128                 // 32 tf32 per row
#define A_STAGE_BYTES (CTA_M * TILE_ROW_BYTES)   // 16 KB
#define B_STAGE_BYTES (CTA_N * TILE_ROW_BYTES)   // 16 KB
#define STAGE_BYTES (A_STAGE_BYTES + B_STAGE_BYTES)
#define SMEM_TOTAL (STAGES * STAGE_BYTES)        // 160 KB

#define GRID_M (M_DIM / CTA_M)             // 64
#define GRID_N (N_DIM / CTA_N)             // 32

// Scratch (device globals: no allocation allowed anywhere)
__device__ float g_W[(size_t)N_DIM * (size_t)K_DIM];
__device__ float g_X[(size_t)M_DIM * (size_t)K_DIM];

// ---------------------------------------------------------------------------
// helpers
// ---------------------------------------------------------------------------
__device__ __forceinline__ uint32_t smem_u32(const void* p) {
    uint32_t a;
    asm("{ .reg .u64 t; cvta.to.shared.u64 t, %1; cvt.u32.u64 %0, t; }" : "=r"(a) : "l"(p));
    return a;
}

#define SWZ(x) ((x) ^ (((x) >> 3) & 0x70))

#define CP_ASYNC16(dst, src) \
    asm volatile("cp.async.cg.shared.global [%0], [%1], 16;" :: "r"(dst), "l"(src) : "memory")
#define CP_ASYNC_COMMIT() asm volatile("cp.async.commit_group;" ::: "memory")
#define CP_ASYNC_WAIT3()  asm volatile("cp.async.wait_group 3;" ::: "memory")

__device__ __forceinline__ void ldsm4(uint32_t* d, uint32_t addr) {
    asm volatile("ldmatrix.sync.aligned.m8n8.x4.shared.b16 {%0,%1,%2,%3}, [%4];"
                 : "=r"(d[0]), "=r"(d[1]), "=r"(d[2]), "=r"(d[3]) : "r"(addr));
}

__device__ __forceinline__ void mma_tf32(float* c, const uint32_t* a, const uint32_t* b) {
    asm volatile(
        "mma.sync.aligned.m16n8k8.row.col.f32.tf32.tf32.f32 "
        "{%0,%1,%2,%3}, {%4,%5,%6,%7}, {%8,%9}, {%0,%1,%2,%3};"
        : "+f"(c[0]), "+f"(c[1]), "+f"(c[2]), "+f"(c[3])
        : "r"(a[0]), "r"(a[1]), "r"(a[2]), "r"(a[3]), "r"(b[0]), "r"(b[1]));
}

__device__ __forceinline__ float tf32_rna(float v) {
    float o;
    asm("cvt.rna.tf32.f32 %0, %1;" : "=f"(o) : "f"(v));
    return o;
}

// ---------------------------------------------------------------------------
// Prep kernels
// ---------------------------------------------------------------------------
__global__ void prep_w_kernel(const float* __restrict__ W, float* __restrict__ out) {
    int idx = blockIdx.x * blockDim.x + threadIdx.x;
    if (idx >= N_DIM * K_DIM) return;
    int r = idx >> 12;
    int c = idx & (K_DIM - 1);
    float v = __ldg(W + idx);
    if (r < 4092 && c < 4092) {   // 341*12 = 4092 core; ragged edge untouched
        int pr = r - (r % 12) + (c % 12);
        int pc = c - (c % 12) + (r % 12);
        v = 0.5f * (v + __ldg(W + pr * K_DIM + pc));
    }
    out[idx] = tf32_rna(v);
}

__global__ void prep_x_kernel(const float4* __restrict__ x, float4* __restrict__ o, int n4) {
    int i = blockIdx.x * blockDim.x + threadIdx.x;
    if (i >= n4) return;
    float4 v = __ldg(x + i);
    v.x = tf32_rna(v.x); v.y = tf32_rna(v.y);
    v.z = tf32_rna(v.z); v.w = tf32_rna(v.w);
    o[i] = v;
}

// ---------------------------------------------------------------------------
// GEMM
// ---------------------------------------------------------------------------
__device__ __forceinline__ void load_stage(uint32_t smem_base, int kiter,
                                           const float* gA, const float* gB, int tid) {
    int slot = kiter % STAGES;
    uint32_t a_base = smem_base + slot * STAGE_BYTES;
    uint32_t b_base = a_base + A_STAGE_BYTES;
    const float* gAk = gA + (size_t)kiter * CTA_K;
    const float* gBk = gB + (size_t)kiter * CTA_K;
#pragma unroll
    for (int i = 0; i < 4; ++i) {
        int c = tid + i * THREADS;          // 0..1023: (row 0..127) x (16B chunk 0..7)
        int row = c >> 3;
        int kc = c & 7;
        uint32_t off = SWZ((uint32_t)(row * TILE_ROW_BYTES + kc * 16));
        CP_ASYNC16(a_base + off, gAk + (size_t)row * K_DIM + kc * 4);
        CP_ASYNC16(b_base + off, gBk + (size_t)row * K_DIM + kc * 4);
    }
    CP_ASYNC_COMMIT();
}

__global__ void __launch_bounds__(THREADS, 1)
gemm_tf32_kernel(const float* __restrict__ X, const float* __restrict__ W,
                 const float* __restrict__ bias, float* __restrict__ out) {
    extern __shared__ char smem[];
    uint32_t smem_base = smem_u32(smem);
    int tid = threadIdx.x;
    int wid = tid >> 5;
    int lid = tid & 31;

    // warp grid: 2 (M) x 4 (N); warp tile 64x32
    int warp_m = wid & 1;
    int warp_n = wid >> 1;

    // Rasterize with GROUP_M=8 for L2 locality
    int pid = blockIdx.x;                  // 0..2047
    const int PPG = 8 * GRID_N;            // 256
    int group = pid / PPG;
    int inpg = pid % PPG;
    int tm = group * 8 + (inpg & 7);
    int tn = inpg >> 3;
    int m0 = tm * CTA_M;
    int n0 = tn * CTA_N;

    const float* gA = X + (size_t)m0 * K_DIM;
    const float* gB = W + (size_t)n0 * K_DIM;

    // ---- per-lane ldmatrix row offsets (bytes, pre-swizzle) ----
    int q = lid >> 3;                      // matrix index within x4
    int r8 = lid & 7;
    // A: matrices [rows0-7,klo][rows8-15,klo][rows0-7,khi][rows8-15,khi]
    int a_row_in = ((q & 1) << 3) + r8;    // row within m16 tile
    int a_gsel = q >> 1;                   // 0 = klo granule, 1 = khi
    uint32_t a_rowb[4];
#pragma unroll
    for (int mt = 0; mt < 4; ++mt)
        a_rowb[mt] = (uint32_t)((warp_m * 64 + mt * 16 + a_row_in) * TILE_ROW_BYTES);
    // B: matrices [tile j0,klo][tile j0,khi][tile j1,klo][tile j1,khi]
    int b_tile_in = q >> 1;                // n8 tile within pair
    int b_gsel = q & 1;
    uint32_t b_rowb[2];
#pragma unroll
    for (int p = 0; p < 2; ++p)
        b_rowb[p] = (uint32_t)((warp_n * 32 + p * 16 + b_tile_in * 8 + r8) * TILE_ROW_BYTES);

    float acc[4][4][4];                    // [m16 tile][n8 tile][frag]
#pragma unroll
    for (int i = 0; i < 4; ++i)
#pragma unroll
        for (int j = 0; j < 4; ++j)
#pragma unroll
            for (int k = 0; k < 4; ++k) acc[i][j][k] = 0.0f;

    // Prologue: fill 4 stages
#pragma unroll
    for (int j = 0; j < STAGES - 1; ++j) load_stage(smem_base, j, gA, gB, tid);

    uint32_t af[2][4][4];
    uint32_t bf[2][2][4];

    for (int it = 0; it < NK_ITERS; ++it) {
        CP_ASYNC_WAIT3();                  // stage `it` landed (4 groups pending -> <=3)
        __syncthreads();                   // all warps done with stage it-1 slot
        if (it + STAGES - 1 < NK_ITERS) load_stage(smem_base, it + STAGES - 1, gA, gB, tid);
        else CP_ASYNC_COMMIT();            // keep group-count invariant exact

        uint32_t a_base = smem_base + (it % STAGES) * STAGE_BYTES;
        uint32_t b_base = a_base + A_STAGE_BYTES;

        // preload k-step 0 fragments
#pragma unroll
        for (int mt = 0; mt < 4; ++mt)
            ldsm4(af[0][mt], a_base + SWZ(a_rowb[mt] + (uint32_t)(a_gsel * 16)));
#pragma unroll
        for (int p = 0; p < 2; ++p)
            ldsm4(bf[0][p], b_base + SWZ(b_rowb[p] + (uint32_t)(b_gsel * 16)));

#pragma unroll
        for (int s = 0; s < 4; ++s) {
            int cur = s & 1;
            if (s < 3) {
                int nxt = cur ^ 1;
                uint32_t koff = (uint32_t)((s + 1) * 32);
#pragma unroll
                for (int mt = 0; mt < 4; ++mt)
                    ldsm4(af[nxt][mt], a_base + SWZ(a_rowb[mt] + koff + (uint32_t)(a_gsel * 16)));
#pragma unroll
                for (int p = 0; p < 2; ++p)
                    ldsm4(bf[nxt][p], b_base + SWZ(b_rowb[p] + koff + (uint32_t)(b_gsel * 16)));
            }
#pragma unroll
            for (int mt = 0; mt < 4; ++mt) {
#pragma unroll
                for (int p = 0; p < 2; ++p) {
                    mma_tf32(acc[mt][2 * p + 0], af[cur][mt], &bf[cur][p][0]);
                    mma_tf32(acc[mt][2 * p + 1], af[cur][mt], &bf[cur][p][2]);
                }
            }
        }
    }

    // ---- epilogue: bias + store ----
    int row_base = m0 + warp_m * 64 + (lid >> 2);
    int col_base = n0 + warp_n * 32 + 2 * (lid & 3);
#pragma unroll
    for (int mt = 0; mt < 4; ++mt) {
#pragma unroll
        for (int j = 0; j < 4; ++j) {
            int col = col_base + j * 8;
            float2 b2 = *reinterpret_cast<const float2*>(bias + col);
            int row = row_base + mt * 16;
            float2 v0, v1;
            v0.x = acc[mt][j][0] + b2.x;
            v0.y = acc[mt][j][1] + b2.y;
            v1.x = acc[mt][j][2] + b2.x;
            v1.y = acc[mt][j][3] + b2.y;
            *reinterpret_cast<float2*>(out + (size_t)row * N_DIM + col) = v0;
            *reinterpret_cast<float2*>(out + (size_t)(row + 8) * N_DIM + col) = v1;
        }
    }
}

// ---------------------------------------------------------------------------
// Launch
// ---------------------------------------------------------------------------
extern "C" void kernel_launch(void* const* d_in, const int* in_sizes, int n_in,
                              void* d_out, int out_size) {
    const float* x = (const float*)d_in[0];
    const float* w = (const float*)d_in[1];
    const float* b = (const float*)d_in[2];
    float* out = (float*)d_out;

    float* gw = nullptr;
    float* gx = nullptr;
    cudaGetSymbolAddress((void**)&gw, g_W);
    cudaGetSymbolAddress((void**)&gx, g_X);

    cudaFuncSetAttribute(gemm_tf32_kernel,
                         cudaFuncAttributeMaxDynamicSharedMemorySize, SMEM_TOTAL);

    prep_w_kernel<<<(N_DIM * K_DIM + 255) / 256, 256>>>(w, gw);
    int n4 = (M_DIM * K_DIM) / 4;
    prep_x_kernel<<<(n4 + 255) / 256, 256>>>((const float4*)x, (float4*)gx, n4);

    gemm_tf32_kernel<<<GRID_M * GRID_N, THREADS, SMEM_TOTAL>>>(gx, gw, b, out);
}

// round 7
// speedup vs baseline: 1.1802x; 1.1802x over previous
#include <cuda_runtime.h>
#include <cstdint>
#include <cstddef>

// ============================================================================
// out[8192,4096] = x[8192,4096] @ sym12x12(W)[4096,4096]^T + bias
// Base-sm_103 feature set (no tcgen05): warp-level mma.sync tf32 GEMM.
// R7: CTA 256x128x32, 4-stage cp.async, 8 warps x (64x64) warp tiles,
//     double-buffered ldmatrix fragments. Prep: W symmetrize+RNA, x RNA.
// ============================================================================

#define M_DIM 8192
#define N_DIM 4096
#define K_DIM 4096

#define CTA_M 256
#define CTA_N 128
#define CTA_K 32
#define STAGES 4
#define THREADS 256
#define NK_ITERS (K_DIM / CTA_K)          // 128

#define TILE_ROW_BYTES 128                 // 32 tf32 per row
#define A_STAGE_BYTES (CTA_M * TILE_ROW_BYTES)   // 32 KB
#define B_STAGE_BYTES (CTA_N * TILE_ROW_BYTES)   // 16 KB
#define STAGE_BYTES (A_STAGE_BYTES + B_STAGE_BYTES)  // 48 KB
#define SMEM_TOTAL (STAGES * STAGE_BYTES)            // 192 KB

#define GRID_M (M_DIM / CTA_M)             // 32
#define GRID_N (N_DIM / CTA_N)             // 32

// Scratch (device globals: no allocation allowed anywhere)
__device__ float g_W[(size_t)N_DIM * (size_t)K_DIM];
__device__ float g_X[(size_t)M_DIM * (size_t)K_DIM];

// ---------------------------------------------------------------------------
// helpers
// ---------------------------------------------------------------------------
__device__ __forceinline__ uint32_t smem_u32(const void* p) {
    uint32_t a;
    asm("{ .reg .u64 t; cvta.to.shared.u64 t, %1; cvt.u32.u64 %0, t; }" : "=r"(a) : "l"(p));
    return a;
}

#define SWZ(x) ((x) ^ (((x) >> 3) & 0x70))

#define CP_ASYNC16(dst, src) \
    asm volatile("cp.async.cg.shared.global [%0], [%1], 16;" :: "r"(dst), "l"(src) : "memory")
#define CP_ASYNC_COMMIT() asm volatile("cp.async.commit_group;" ::: "memory")
#define CP_ASYNC_WAIT2()  asm volatile("cp.async.wait_group 2;" ::: "memory")

__device__ __forceinline__ void ldsm4(uint32_t* d, uint32_t addr) {
    asm volatile("ldmatrix.sync.aligned.m8n8.x4.shared.b16 {%0,%1,%2,%3}, [%4];"
                 : "=r"(d[0]), "=r"(d[1]), "=r"(d[2]), "=r"(d[3]) : "r"(addr));
}

__device__ __forceinline__ void mma_tf32(float* c, const uint32_t* a, const uint32_t* b) {
    asm volatile(
        "mma.sync.aligned.m16n8k8.row.col.f32.tf32.tf32.f32 "
        "{%0,%1,%2,%3}, {%4,%5,%6,%7}, {%8,%9}, {%0,%1,%2,%3};"
        : "+f"(c[0]), "+f"(c[1]), "+f"(c[2]), "+f"(c[3])
        : "r"(a[0]), "r"(a[1]), "r"(a[2]), "r"(a[3]), "r"(b[0]), "r"(b[1]));
}

__device__ __forceinline__ float tf32_rna(float v) {
    float o;
    asm("cvt.rna.tf32.f32 %0, %1;" : "=f"(o) : "f"(v));
    return o;
}

// ---------------------------------------------------------------------------
// Prep kernels
// ---------------------------------------------------------------------------
__global__ void prep_w_kernel(const float* __restrict__ W, float* __restrict__ out) {
    int idx = blockIdx.x * blockDim.x + threadIdx.x;
    if (idx >= N_DIM * K_DIM) return;
    int r = idx >> 12;
    int c = idx & (K_DIM - 1);
    float v = __ldg(W + idx);
    if (r < 4092 && c < 4092) {   // 341*12 = 4092 core; ragged edge untouched
        int pr = r - (r % 12) + (c % 12);
        int pc = c - (c % 12) + (r % 12);
        v = 0.5f * (v + __ldg(W + pr * K_DIM + pc));
    }
    out[idx] = tf32_rna(v);
}

__global__ void prep_x_kernel(const float4* __restrict__ x, float4* __restrict__ o, int n4) {
    int i = blockIdx.x * blockDim.x + threadIdx.x;
    if (i >= n4) return;
    float4 v = __ldg(x + i);
    v.x = tf32_rna(v.x); v.y = tf32_rna(v.y);
    v.z = tf32_rna(v.z); v.w = tf32_rna(v.w);
    o[i] = v;
}

// ---------------------------------------------------------------------------
// GEMM
// ---------------------------------------------------------------------------
__device__ __forceinline__ void load_stage(uint32_t smem_base, int kiter,
                                           const float* gA, const float* gB, int tid) {
    int slot = kiter % STAGES;
    uint32_t a_base = smem_base + slot * STAGE_BYTES;
    uint32_t b_base = a_base + A_STAGE_BYTES;
    const float* gAk = gA + (size_t)kiter * CTA_K;
    const float* gBk = gB + (size_t)kiter * CTA_K;
    // A: 256 rows x 8 chunks = 2048 -> 8 per thread
#pragma unroll
    for (int i = 0; i < 8; ++i) {
        int c = tid + i * THREADS;
        int row = c >> 3;
        int kc = c & 7;
        uint32_t off = SWZ((uint32_t)(row * TILE_ROW_BYTES + kc * 16));
        CP_ASYNC16(a_base + off, gAk + (size_t)row * K_DIM + kc * 4);
    }
    // B: 128 rows x 8 chunks = 1024 -> 4 per thread
#pragma unroll
    for (int i = 0; i < 4; ++i) {
        int c = tid + i * THREADS;
        int row = c >> 3;
        int kc = c & 7;
        uint32_t off = SWZ((uint32_t)(row * TILE_ROW_BYTES + kc * 16));
        CP_ASYNC16(b_base + off, gBk + (size_t)row * K_DIM + kc * 4);
    }
    CP_ASYNC_COMMIT();
}

__global__ void __launch_bounds__(THREADS, 1)
gemm_tf32_kernel(const float* __restrict__ X, const float* __restrict__ W,
                 const float* __restrict__ bias, float* __restrict__ out) {
    extern __shared__ char smem[];
    uint32_t smem_base = smem_u32(smem);
    int tid = threadIdx.x;
    int wid = tid >> 5;
    int lid = tid & 31;

    // warp grid: 4 (M) x 2 (N); warp tile 64x64
    int warp_m = wid & 3;
    int warp_n = wid >> 2;

    // Rasterize with GROUP_M=4 for L2 locality
    int pid = blockIdx.x;                  // 0..1023
    const int PPG = 4 * GRID_N;            // 128
    int group = pid / PPG;
    int inpg = pid % PPG;
    int tm = group * 4 + (inpg & 3);
    int tn = inpg >> 2;
    int m0 = tm * CTA_M;
    int n0 = tn * CTA_N;

    const float* gA = X + (size_t)m0 * K_DIM;
    const float* gB = W + (size_t)n0 * K_DIM;

    // ---- per-lane ldmatrix row offsets (bytes, pre-swizzle) ----
    int q = lid >> 3;                      // matrix index within x4
    int r8 = lid & 7;
    // A x4: matrices [rows0-7,g0][rows8-15,g0][rows0-7,g1][rows8-15,g1]
    int a_row_in = ((q & 1) << 3) + r8;    // row within m16 tile
    int a_gsel = q >> 1;                   // 16B granule (k0-3 / k4-7)
    uint32_t a_rowb[4];
#pragma unroll
    for (int mt = 0; mt < 4; ++mt)
        a_rowb[mt] = (uint32_t)((warp_m * 64 + mt * 16 + a_row_in) * TILE_ROW_BYTES);
    // B x4: matrices [n8 tile q>>1 within pair, granule q&1]
    int b_tile_in = q >> 1;
    int b_gsel = q & 1;
    uint32_t b_rowb[4];                    // 4 n16-pairs cover n64
#pragma unroll
    for (int p = 0; p < 4; ++p)
        b_rowb[p] = (uint32_t)((warp_n * 64 + p * 16 + b_tile_in * 8 + r8) * TILE_ROW_BYTES);

    float acc[4][8][4];                    // [m16 tile][n8 tile][frag]
#pragma unroll
    for (int i = 0; i < 4; ++i)
#pragma unroll
        for (int j = 0; j < 8; ++j)
#pragma unroll
            for (int k = 0; k < 4; ++k) acc[i][j][k] = 0.0f;

    // Prologue: fill 3 stages
#pragma unroll
    for (int j = 0; j < STAGES - 1; ++j) load_stage(smem_base, j, gA, gB, tid);

    uint32_t af[2][4][4];
    uint32_t bf[2][4][4];

    for (int it = 0; it < NK_ITERS; ++it) {
        CP_ASYNC_WAIT2();                  // stage `it` landed (3 groups pending -> <=2)
        __syncthreads();                   // all warps done with stage it-1 slot
        if (it + STAGES - 1 < NK_ITERS) load_stage(smem_base, it + STAGES - 1, gA, gB, tid);
        else CP_ASYNC_COMMIT();            // keep group-count invariant exact

        uint32_t a_base = smem_base + (it % STAGES) * STAGE_BYTES;
        uint32_t b_base = a_base + A_STAGE_BYTES;

        // preload k-step 0 fragments
#pragma unroll
        for (int mt = 0; mt < 4; ++mt)
            ldsm4(af[0][mt], a_base + SWZ(a_rowb[mt] + (uint32_t)(a_gsel * 16)));
#pragma unroll
        for (int p = 0; p < 4; ++p)
            ldsm4(bf[0][p], b_base + SWZ(b_rowb[p] + (uint32_t)(b_gsel * 16)));

#pragma unroll
        for (int s = 0; s < 4; ++s) {
            int cur = s & 1;
            if (s < 3) {
                int nxt = cur ^ 1;
                uint32_t koff = (uint32_t)((s + 1) * 32);
#pragma unroll
                for (int mt = 0; mt < 4; ++mt)
                    ldsm4(af[nxt][mt], a_base + SWZ(a_rowb[mt] + koff + (uint32_t)(a_gsel * 16)));
#pragma unroll
                for (int p = 0; p < 4; ++p)
                    ldsm4(bf[nxt][p], b_base + SWZ(b_rowb[p] + koff + (uint32_t)(b_gsel * 16)));
            }
#pragma unroll
            for (int mt = 0; mt < 4; ++mt) {
#pragma unroll
                for (int j = 0; j < 8; ++j)
                    mma_tf32(acc[mt][j], af[cur][mt], &bf[cur][j >> 1][2 * (j & 1)]);
            }
        }
    }

    // ---- epilogue: bias + store ----
    int row_base = m0 + warp_m * 64 + (lid >> 2);
    int col_base = n0 + warp_n * 64 + 2 * (lid & 3);
#pragma unroll
    for (int mt = 0; mt < 4; ++mt) {
#pragma unroll
        for (int j = 0; j < 8; ++j) {
            int col = col_base + j * 8;
            float2 b2 = *reinterpret_cast<const float2*>(bias + col);
            int row = row_base + mt * 16;
            float2 v0, v1;
            v0.x = acc[mt][j][0] + b2.x;
            v0.y = acc[mt][j][1] + b2.y;
            v1.x = acc[mt][j][2] + b2.x;
            v1.y = acc[mt][j][3] + b2.y;
            *reinterpret_cast<float2*>(out + (size_t)row * N_DIM + col) = v0;
            *reinterpret_cast<float2*>(out + (size_t)(row + 8) * N_DIM + col) = v1;
        }
    }
}

// ---------------------------------------------------------------------------
// Launch
// ---------------------------------------------------------------------------
extern "C" void kernel_launch(void* const* d_in, const int* in_sizes, int n_in,
                              void* d_out, int out_size) {
    const float* x = (const float*)d_in[0];
    const float* w = (const float*)d_in[1];
    const float* b = (const float*)d_in[2];
    float* out = (float*)d_out;

    float* gw = nullptr;
    float* gx = nullptr;
    cudaGetSymbolAddress((void**)&gw, g_W);
    cudaGetSymbolAddress((void**)&gx, g_X);

    cudaFuncSetAttribute(gemm_tf32_kernel,
                         cudaFuncAttributeMaxDynamicSharedMemorySize, SMEM_TOTAL);

    prep_w_kernel<<<(N_DIM * K_DIM + 255) / 256, 256>>>(w, gw);
    int n4 = (M_DIM * K_DIM) / 4;
    prep_x_kernel<<<(n4 + 255) / 256, 256>>>((const float4*)x, (float4*)gx, n4);

    gemm_tf32_kernel<<<GRID_M * GRID_N, THREADS, SMEM_TOTAL>>>(gx, gw, b, out);
}

// round 8
// speedup vs baseline: 2.1994x; 1.8636x over previous
#include <cuda_runtime.h>
#include <cuda_fp16.h>
#include <cstdint>
#include <cstddef>

// ============================================================================
// out[8192,4096] = x[8192,4096] @ sym12x12(W)[4096,4096]^T + bias
// R8: fp16 m16n8k16 mma.sync (same 11-bit mantissa as tf32, half the HMMA
// instruction count, half the memory traffic). CTA 256x128x64, 4-stage
// cp.async, 8 warps x (64x64) tiles, fp32 accumulation.
// ============================================================================

#define M_DIM 8192
#define N_DIM 4096
#define K_DIM 4096

#define CTA_M 256
#define CTA_N 128
#define CTA_K 64
#define STAGES 4
#define THREADS 256
#define NK_ITERS (K_DIM / CTA_K)          // 64

#define TILE_ROW_BYTES 128                 // 64 fp16 per row
#define A_STAGE_BYTES (CTA_M * TILE_ROW_BYTES)   // 32 KB
#define B_STAGE_BYTES (CTA_N * TILE_ROW_BYTES)   // 16 KB
#define STAGE_BYTES (A_STAGE_BYTES + B_STAGE_BYTES)  // 48 KB
#define SMEM_TOTAL (STAGES * STAGE_BYTES)            // 192 KB

#define GRID_M (M_DIM / CTA_M)             // 32
#define GRID_N (N_DIM / CTA_N)             // 32

// Scratch as uint4 arrays for guaranteed 16B alignment (cp.async sources)
__device__ uint4 g_W4[(size_t)N_DIM * (size_t)K_DIM / 8];
__device__ uint4 g_X4[(size_t)M_DIM * (size_t)K_DIM / 8];

// ---------------------------------------------------------------------------
// helpers
// ---------------------------------------------------------------------------
__device__ __forceinline__ uint32_t smem_u32(const void* p) {
    uint32_t a;
    asm("{ .reg .u64 t; cvta.to.shared.u64 t, %1; cvt.u32.u64 %0, t; }" : "=r"(a) : "l"(p));
    return a;
}

#define SWZ(x) ((x) ^ (((x) >> 3) & 0x70))

#define CP_ASYNC16(dst, src) \
    asm volatile("cp.async.cg.shared.global [%0], [%1], 16;" :: "r"(dst), "l"(src) : "memory")
#define CP_ASYNC_COMMIT() asm volatile("cp.async.commit_group;" ::: "memory")
#define CP_ASYNC_WAIT2()  asm volatile("cp.async.wait_group 2;" ::: "memory")

__device__ __forceinline__ void ldsm4(uint32_t* d, uint32_t addr) {
    asm volatile("ldmatrix.sync.aligned.m8n8.x4.shared.b16 {%0,%1,%2,%3}, [%4];"
                 : "=r"(d[0]), "=r"(d[1]), "=r"(d[2]), "=r"(d[3]) : "r"(addr));
}

__device__ __forceinline__ void mma_f16(float* c, const uint32_t* a, const uint32_t* b) {
    asm volatile(
        "mma.sync.aligned.m16n8k16.row.col.f32.f16.f16.f32 "
        "{%0,%1,%2,%3}, {%4,%5,%6,%7}, {%8,%9}, {%0,%1,%2,%3};"
        : "+f"(c[0]), "+f"(c[1]), "+f"(c[2]), "+f"(c[3])
        : "r"(a[0]), "r"(a[1]), "r"(a[2]), "r"(a[3]), "r"(b[0]), "r"(b[1]));
}

// ---------------------------------------------------------------------------
// Prep kernels
// ---------------------------------------------------------------------------
__global__ void prep_w_kernel(const float* __restrict__ W, __half* __restrict__ out) {
    int idx = blockIdx.x * blockDim.x + threadIdx.x;
    if (idx >= N_DIM * K_DIM) return;
    int r = idx >> 12;
    int c = idx & (K_DIM - 1);
    float v = __ldg(W + idx);
    if (r < 4092 && c < 4092) {   // 341*12 = 4092 core; ragged edge untouched
        int pr = r - (r % 12) + (c % 12);
        int pc = c - (c % 12) + (r % 12);
        v = 0.5f * (v + __ldg(W + pr * K_DIM + pc));
    }
    out[idx] = __float2half_rn(v);
}

// 8 floats -> 8 halves (one 16B store) per thread
__global__ void prep_x_kernel(const float4* __restrict__ x, uint4* __restrict__ o, int n8) {
    int i = blockIdx.x * blockDim.x + threadIdx.x;
    if (i >= n8) return;
    float4 v0 = __ldg(x + 2 * i);
    float4 v1 = __ldg(x + 2 * i + 1);
    __half2 h0 = __floats2half2_rn(v0.x, v0.y);
    __half2 h1 = __floats2half2_rn(v0.z, v0.w);
    __half2 h2 = __floats2half2_rn(v1.x, v1.y);
    __half2 h3 = __floats2half2_rn(v1.z, v1.w);
    uint4 u;
    u.x = *reinterpret_cast<uint32_t*>(&h0);
    u.y = *reinterpret_cast<uint32_t*>(&h1);
    u.z = *reinterpret_cast<uint32_t*>(&h2);
    u.w = *reinterpret_cast<uint32_t*>(&h3);
    o[i] = u;
}

// ---------------------------------------------------------------------------
// GEMM
// ---------------------------------------------------------------------------
__device__ __forceinline__ void load_stage(uint32_t smem_base, int kiter,
                                           const __half* gA, const __half* gB, int tid) {
    int slot = kiter % STAGES;
    uint32_t a_base = smem_base + slot * STAGE_BYTES;
    uint32_t b_base = a_base + A_STAGE_BYTES;
    const __half* gAk = gA + (size_t)kiter * CTA_K;
    const __half* gBk = gB + (size_t)kiter * CTA_K;
    // A: 256 rows x 8 16B-chunks = 2048 -> 8 per thread
#pragma unroll
    for (int i = 0; i < 8; ++i) {
        int c = tid + i * THREADS;
        int row = c >> 3;
        int kc = c & 7;
        uint32_t off = SWZ((uint32_t)(row * TILE_ROW_BYTES + kc * 16));
        CP_ASYNC16(a_base + off, gAk + (size_t)row * K_DIM + kc * 8);
    }
    // B: 128 rows x 8 chunks = 1024 -> 4 per thread
#pragma unroll
    for (int i = 0; i < 4; ++i) {
        int c = tid + i * THREADS;
        int row = c >> 3;
        int kc = c & 7;
        uint32_t off = SWZ((uint32_t)(row * TILE_ROW_BYTES + kc * 16));
        CP_ASYNC16(b_base + off, gBk + (size_t)row * K_DIM + kc * 8);
    }
    CP_ASYNC_COMMIT();
}

__global__ void __launch_bounds__(THREADS, 1)
gemm_f16_kernel(const __half* __restrict__ X, const __half* __restrict__ W,
                const float* __restrict__ bias, float* __restrict__ out) {
    extern __shared__ char smem[];
    uint32_t smem_base = smem_u32(smem);
    int tid = threadIdx.x;
    int wid = tid >> 5;
    int lid = tid & 31;

    // warp grid: 4 (M) x 2 (N); warp tile 64x64
    int warp_m = wid & 3;
    int warp_n = wid >> 2;

    // Rasterize with GROUP_M=4 for L2 locality
    int pid = blockIdx.x;                  // 0..1023
    const int PPG = 4 * GRID_N;            // 128
    int group = pid / PPG;
    int inpg = pid % PPG;
    int tm = group * 4 + (inpg & 3);
    int tn = inpg >> 2;
    int m0 = tm * CTA_M;
    int n0 = tn * CTA_N;

    const __half* gA = X + (size_t)m0 * K_DIM;
    const __half* gB = W + (size_t)n0 * K_DIM;

    // ---- per-lane ldmatrix row offsets (bytes, pre-swizzle) ----
    // One 16B granule = 8 fp16 = half of a k16 step.
    int q = lid >> 3;                      // matrix index within x4
    int r8 = lid & 7;
    // A x4: [rows0-7,klo][rows8-15,klo][rows0-7,khi][rows8-15,khi]
    int a_row_in = ((q & 1) << 3) + r8;
    int a_gsel = q >> 1;
    uint32_t a_rowb[4];
#pragma unroll
    for (int mt = 0; mt < 4; ++mt)
        a_rowb[mt] = (uint32_t)((warp_m * 64 + mt * 16 + a_row_in) * TILE_ROW_BYTES);
    // B x4: [n8-tile q>>1 within n16 pair, k-granule q&1]
    int b_tile_in = q >> 1;
    int b_gsel = q & 1;
    uint32_t b_rowb[4];                    // 4 n16-pairs cover n64
#pragma unroll
    for (int p = 0; p < 4; ++p)
        b_rowb[p] = (uint32_t)((warp_n * 64 + p * 16 + b_tile_in * 8 + r8) * TILE_ROW_BYTES);

    float acc[4][8][4];                    // [m16 tile][n8 tile][frag]
#pragma unroll
    for (int i = 0; i < 4; ++i)
#pragma unroll
        for (int j = 0; j < 8; ++j)
#pragma unroll
            for (int k = 0; k < 4; ++k) acc[i][j][k] = 0.0f;

    // Prologue: fill 3 stages
#pragma unroll
    for (int j = 0; j < STAGES - 1; ++j) load_stage(smem_base, j, gA, gB, tid);

    uint32_t af[2][4][4];
    uint32_t bf[2][4][4];

    for (int it = 0; it < NK_ITERS; ++it) {
        CP_ASYNC_WAIT2();                  // stage `it` landed (3 pending -> <=2)
        __syncthreads();                   // all warps done with reused slot
        if (it + STAGES - 1 < NK_ITERS) load_stage(smem_base, it + STAGES - 1, gA, gB, tid);
        else CP_ASYNC_COMMIT();            // keep group-count invariant exact

        uint32_t a_base = smem_base + (it % STAGES) * STAGE_BYTES;
        uint32_t b_base = a_base + A_STAGE_BYTES;

        // preload k16-step 0 fragments
#pragma unroll
        for (int mt = 0; mt < 4; ++mt)
            ldsm4(af[0][mt], a_base + SWZ(a_rowb[mt] + (uint32_t)(a_gsel * 16)));
#pragma unroll
        for (int p = 0; p < 4; ++p)
            ldsm4(bf[0][p], b_base + SWZ(b_rowb[p] + (uint32_t)(b_gsel * 16)));

#pragma unroll
        for (int s = 0; s < 4; ++s) {      // 4 k16-steps cover CTA_K=64
            int cur = s & 1;
            if (s < 3) {
                int nxt = cur ^ 1;
                uint32_t koff = (uint32_t)((s + 1) * 32);   // 32B per k16 step
#pragma unroll
                for (int mt = 0; mt < 4; ++mt)
                    ldsm4(af[nxt][mt], a_base + SWZ(a_rowb[mt] + koff + (uint32_t)(a_gsel * 16)));
#pragma unroll
                for (int p = 0; p < 4; ++p)
                    ldsm4(bf[nxt][p], b_base + SWZ(b_rowb[p] + koff + (uint32_t)(b_gsel * 16)));
            }
#pragma unroll
            for (int mt = 0; mt < 4; ++mt) {
#pragma unroll
                for (int j = 0; j < 8; ++j)
                    mma_f16(acc[mt][j], af[cur][mt], &bf[cur][j >> 1][2 * (j & 1)]);
            }
        }
    }

    // ---- epilogue: bias + store ----
    int row_base = m0 + warp_m * 64 + (lid >> 2);
    int col_base = n0 + warp_n * 64 + 2 * (lid & 3);
#pragma unroll
    for (int mt = 0; mt < 4; ++mt) {
#pragma unroll
        for (int j = 0; j < 8; ++j) {
            int col = col_base + j * 8;
            float2 b2 = *reinterpret_cast<const float2*>(bias + col);
            int row = row_base + mt * 16;
            float2 v0, v1;
            v0.x = acc[mt][j][0] + b2.x;
            v0.y = acc[mt][j][1] + b2.y;
            v1.x = acc[mt][j][2] + b2.x;
            v1.y = acc[mt][j][3] + b2.y;
            *reinterpret_cast<float2*>(out + (size_t)row * N_DIM + col) = v0;
            *reinterpret_cast<float2*>(out + (size_t)(row + 8) * N_DIM + col) = v1;
        }
    }
}

// ---------------------------------------------------------------------------
// Launch
// ---------------------------------------------------------------------------
extern "C" void kernel_launch(void* const* d_in, const int* in_sizes, int n_in,
                              void* d_out, int out_size) {
    const float* x = (const float*)d_in[0];
    const float* w = (const float*)d_in[1];
    const float* b = (const float*)d_in[2];
    float* out = (float*)d_out;

    void* gwp = nullptr;
    void* gxp = nullptr;
    cudaGetSymbolAddress(&gwp, g_W4);
    cudaGetSymbolAddress(&gxp, g_X4);
    __half* gw = (__half*)gwp;
    __half* gx = (__half*)gxp;

    cudaFuncSetAttribute(gemm_f16_kernel,
                         cudaFuncAttributeMaxDynamicSharedMemorySize, SMEM_TOTAL);

    prep_w_kernel<<<(N_DIM * K_DIM + 255) / 256, 256>>>(w, gw);
    int n8 = (M_DIM * K_DIM) / 8;
    prep_x_kernel<<<(n8 + 255) / 256, 256>>>((const float4*)x, (uint4*)gx, n8);

    gemm_f16_kernel<<<GRID_M * GRID_N, THREADS, SMEM_TOTAL>>>(gx, gw, b, out);
}

// round 10
// speedup vs baseline: 2.2052x; 1.0026x over previous
#include <cuda_runtime.h>
#include <cuda_fp16.h>
#include <cstdint>
#include <cstddef>

// ============================================================================
// out[8192,4096] = x[8192,4096] @ sym12x12(W)[4096,4096]^T + bias
// R9: single fused prep kernel (panel-SMEM W symmetrize+convert, coalesced;
//     x fp32->fp16 pack) + unchanged fp16 m16n8k16 GEMM from R8.
//     Launch cycle is now (prep, gemm) so ncu -s5 -c1 captures the GEMM.
// ============================================================================

#define M_DIM 8192
#define N_DIM 4096
#define K_DIM 4096

#define CTA_M 256
#define CTA_N 128
#define CTA_K 64
#define STAGES 4
#define THREADS 256
#define NK_ITERS (K_DIM / CTA_K)          // 64

#define TILE_ROW_BYTES 128                 // 64 fp16 per row
#define A_STAGE_BYTES (CTA_M * TILE_ROW_BYTES)   // 32 KB
#define B_STAGE_BYTES (CTA_N * TILE_ROW_BYTES)   // 16 KB
#define STAGE_BYTES (A_STAGE_BYTES + B_STAGE_BYTES)  // 48 KB
#define SMEM_TOTAL (STAGES * STAGE_BYTES)            // 192 KB

#define GRID_M (M_DIM / CTA_M)             // 32
#define GRID_N (N_DIM / CTA_N)             // 32

// prep grid layout
#define PANW 516                            // 43 12-blocks per panel
#define NPAN 8                              // 8*516 = 4128 >= 4096
#define NSTRIP 341                          // rows 0..4091 symmetrized core
#define NB_W (NSTRIP * NPAN)                // 2728
#define NB_CLEAN 16                         // rows 4092..4095 convert-only
#define NB_X 16384                          // 16384 * 256 uint4 = 33.5M halves
#define PREP_GRID (NB_W + NB_CLEAN + NB_X)

// Scratch as uint4 arrays for guaranteed 16B alignment (cp.async sources)
__device__ uint4 g_W4[(size_t)N_DIM * (size_t)K_DIM / 8];
__device__ uint4 g_X4[(size_t)M_DIM * (size_t)K_DIM / 8];

// ---------------------------------------------------------------------------
// helpers
// ---------------------------------------------------------------------------
__device__ __forceinline__ uint32_t smem_u32(const void* p) {
    uint32_t a;
    asm("{ .reg .u64 t; cvta.to.shared.u64 t, %1; cvt.u32.u64 %0, t; }" : "=r"(a) : "l"(p));
    return a;
}

#define SWZ(x) ((x) ^ (((x) >> 3) & 0x70))

#define CP_ASYNC16(dst, src) \
    asm volatile("cp.async.cg.shared.global [%0], [%1], 16;" :: "r"(dst), "l"(src) : "memory")
#define CP_ASYNC_COMMIT() asm volatile("cp.async.commit_group;" ::: "memory")
#define CP_ASYNC_WAIT2()  asm volatile("cp.async.wait_group 2;" ::: "memory")

__device__ __forceinline__ void ldsm4(uint32_t* d, uint32_t addr) {
    asm volatile("ldmatrix.sync.aligned.m8n8.x4.shared.b16 {%0,%1,%2,%3}, [%4];"
                 : "=r"(d[0]), "=r"(d[1]), "=r"(d[2]), "=r"(d[3]) : "r"(addr));
}

__device__ __forceinline__ void mma_f16(float* c, const uint32_t* a, const uint32_t* b) {
    asm volatile(
        "mma.sync.aligned.m16n8k16.row.col.f32.f16.f16.f32 "
        "{%0,%1,%2,%3}, {%4,%5,%6,%7}, {%8,%9}, {%0,%1,%2,%3};"
        : "+f"(c[0]), "+f"(c[1]), "+f"(c[2]), "+f"(c[3])
        : "r"(a[0]), "r"(a[1]), "r"(a[2]), "r"(a[3]), "r"(b[0]), "r"(b[1]));
}

// ---------------------------------------------------------------------------
// Fused prep kernel
//   blocks [0, NB_W):            W core panels (12 rows x 516 cols, SMEM sym)
//   blocks [NB_W, NB_W+NB_CLEAN): W rows 4092..4095 convert-only
//   rest:                        x fp32 -> fp16 pack (8 per thread)
// ---------------------------------------------------------------------------
__global__ void __launch_bounds__(256)
prep_kernel(const float* __restrict__ W, __half* __restrict__ gw,
            const float4* __restrict__ x, uint4* __restrict__ gx) {
    int bid = blockIdx.x;
    int tid = threadIdx.x;

    if (bid < NB_W) {
        __shared__ float s[12][517];       // 517 % 32 = 5 -> column gather conflict-free
        int strip = bid / NPAN;
        int pan = bid % NPAN;
        int r0 = strip * 12;
        int c0 = pan * PANW;               // multiple of 12
        // load 12 x 516 panel (coalesced rows)
#pragma unroll
        for (int k = 0; k < 25; ++k) {
            int idx = tid + k * 256;
            if (idx < 12 * PANW) {
                int row = idx / PANW, col = idx - row * PANW;
                int cg = c0 + col;
                if (cg < K_DIM)
                    s[row][col] = __ldg(W + (size_t)(r0 + row) * K_DIM + cg);
            }
        }
        __syncthreads();
        // symmetrize from SMEM, write coalesced fp16
#pragma unroll
        for (int k = 0; k < 25; ++k) {
            int idx = tid + k * 256;
            if (idx < 12 * PANW) {
                int row = idx / PANW, col = idx - row * PANW;
                int cg = c0 + col;
                if (cg < K_DIM) {
                    float v = s[row][col];
                    if (cg < 4092) {       // in symmetrized core (rows always are)
                        int cm = col % 12;
                        v = 0.5f * (v + s[cm][col - cm + row]);
                    }
                    gw[(size_t)(r0 + row) * K_DIM + cg] = __float2half_rn(v);
                }
            }
        }
    } else if (bid < NB_W + NB_CLEAN) {
        // rows 4092..4095: straight convert (16 blocks x 1024 elements)
        int b = bid - NB_W;
        int base = 4092 * K_DIM + b * 1024 + tid * 4;
#pragma unroll
        for (int j = 0; j < 4; ++j)
            gw[base + j] = __float2half_rn(__ldg(W + base + j));
    } else {
        // x: 8 fp32 -> 8 fp16 (one 16B store) per thread
        int i = (bid - NB_W - NB_CLEAN) * 256 + tid;  // uint4 index
        float4 v0 = __ldg(x + 2 * i);
        float4 v1 = __ldg(x + 2 * i + 1);
        __half2 h0 = __floats2half2_rn(v0.x, v0.y);
        __half2 h1 = __floats2half2_rn(v0.z, v0.w);
        __half2 h2 = __floats2half2_rn(v1.x, v1.y);
        __half2 h3 = __floats2half2_rn(v1.z, v1.w);
        uint4 u;
        u.x = *reinterpret_cast<uint32_t*>(&h0);
        u.y = *reinterpret_cast<uint32_t*>(&h1);
        u.z = *reinterpret_cast<uint32_t*>(&h2);
        u.w = *reinterpret_cast<uint32_t*>(&h3);
        gx[i] = u;
    }
}

// ---------------------------------------------------------------------------
// GEMM (unchanged from R8)
// ---------------------------------------------------------------------------
__device__ __forceinline__ void load_stage(uint32_t smem_base, int kiter,
                                           const __half* gA, const __half* gB, int tid) {
    int slot = kiter % STAGES;
    uint32_t a_base = smem_base + slot * STAGE_BYTES;
    uint32_t b_base = a_base + A_STAGE_BYTES;
    const __half* gAk = gA + (size_t)kiter * CTA_K;
    const __half* gBk = gB + (size_t)kiter * CTA_K;
#pragma unroll
    for (int i = 0; i < 8; ++i) {
        int c = tid + i * THREADS;
        int row = c >> 3;
        int kc = c & 7;
        uint32_t off = SWZ((uint32_t)(row * TILE_ROW_BYTES + kc * 16));
        CP_ASYNC16(a_base + off, gAk + (size_t)row * K_DIM + kc * 8);
    }
#pragma unroll
    for (int i = 0; i < 4; ++i) {
        int c = tid + i * THREADS;
        int row = c >> 3;
        int kc = c & 7;
        uint32_t off = SWZ((uint32_t)(row * TILE_ROW_BYTES + kc * 16));
        CP_ASYNC16(b_base + off, gBk + (size_t)row * K_DIM + kc * 8);
    }
    CP_ASYNC_COMMIT();
}

__global__ void __launch_bounds__(THREADS, 1)
gemm_f16_kernel(const __half* __restrict__ X, const __half* __restrict__ W,
                const float* __restrict__ bias, float* __restrict__ out) {
    extern __shared__ char smem[];
    uint32_t smem_base = smem_u32(smem);
    int tid = threadIdx.x;
    int wid = tid >> 5;
    int lid = tid & 31;

    int warp_m = wid & 3;
    int warp_n = wid >> 2;

    int pid = blockIdx.x;
    const int PPG = 4 * GRID_N;            // 128
    int group = pid / PPG;
    int inpg = pid % PPG;
    int tm = group * 4 + (inpg & 3);
    int tn = inpg >> 2;
    int m0 = tm * CTA_M;
    int n0 = tn * CTA_N;

    const __half* gA = X + (size_t)m0 * K_DIM;
    const __half* gB = W + (size_t)n0 * K_DIM;

    int q = lid >> 3;
    int r8 = lid & 7;
    int a_row_in = ((q & 1) << 3) + r8;
    int a_gsel = q >> 1;
    uint32_t a_rowb[4];
#pragma unroll
    for (int mt = 0; mt < 4; ++mt)
        a_rowb[mt] = (uint32_t)((warp_m * 64 + mt * 16 + a_row_in) * TILE_ROW_BYTES);
    int b_tile_in = q >> 1;
    int b_gsel = q & 1;
    uint32_t b_rowb[4];
#pragma unroll
    for (int p = 0; p < 4; ++p)
        b_rowb[p] = (uint32_t)((warp_n * 64 + p * 16 + b_tile_in * 8 + r8) * TILE_ROW_BYTES);

    float acc[4][8][4];
#pragma unroll
    for (int i = 0; i < 4; ++i)
#pragma unroll
        for (int j = 0; j < 8; ++j)
#pragma unroll
            for (int k = 0; k < 4; ++k) acc[i][j][k] = 0.0f;

#pragma unroll
    for (int j = 0; j < STAGES - 1; ++j) load_stage(smem_base, j, gA, gB, tid);

    uint32_t af[2][4][4];
    uint32_t bf[2][4][4];

    for (int it = 0; it < NK_ITERS; ++it) {
        CP_ASYNC_WAIT2();
        __syncthreads();
        if (it + STAGES - 1 < NK_ITERS) load_stage(smem_base, it + STAGES - 1, gA, gB, tid);
        else CP_ASYNC_COMMIT();

        uint32_t a_base = smem_base + (it % STAGES) * STAGE_BYTES;
        uint32_t b_base = a_base + A_STAGE_BYTES;

#pragma unroll
        for (int mt = 0; mt < 4; ++mt)
            ldsm4(af[0][mt], a_base + SWZ(a_rowb[mt] + (uint32_t)(a_gsel * 16)));
#pragma unroll
        for (int p = 0; p < 4; ++p)
            ldsm4(bf[0][p], b_base + SWZ(b_rowb[p] + (uint32_t)(b_gsel * 16)));

#pragma unroll
        for (int s = 0; s < 4; ++s) {
            int cur = s & 1;
            if (s < 3) {
                int nxt = cur ^ 1;
                uint32_t koff = (uint32_t)((s + 1) * 32);
#pragma unroll
                for (int mt = 0; mt < 4; ++mt)
                    ldsm4(af[nxt][mt], a_base + SWZ(a_rowb[mt] + koff + (uint32_t)(a_gsel * 16)));
#pragma unroll
                for (int p = 0; p < 4; ++p)
                    ldsm4(bf[nxt][p], b_base + SWZ(b_rowb[p] + koff + (uint32_t)(b_gsel * 16)));
            }
#pragma unroll
            for (int mt = 0; mt < 4; ++mt) {
#pragma unroll
                for (int j = 0; j < 8; ++j)
                    mma_f16(acc[mt][j], af[cur][mt], &bf[cur][j >> 1][2 * (j & 1)]);
            }
        }
    }

    int row_base = m0 + warp_m * 64 + (lid >> 2);
    int col_base = n0 + warp_n * 64 + 2 * (lid & 3);
#pragma unroll
    for (int mt = 0; mt < 4; ++mt) {
#pragma unroll
        for (int j = 0; j < 8; ++j) {
            int col = col_base + j * 8;
            float2 b2 = *reinterpret_cast<const float2*>(bias + col);
            int row = row_base + mt * 16;
            float2 v0, v1;
            v0.x = acc[mt][j][0] + b2.x;
            v0.y = acc[mt][j][1] + b2.y;
            v1.x = acc[mt][j][2] + b2.x;
            v1.y = acc[mt][j][3] + b2.y;
            *reinterpret_cast<float2*>(out + (size_t)row * N_DIM + col) = v0;
            *reinterpret_cast<float2*>(out + (size_t)(row + 8) * N_DIM + col) = v1;
        }
    }
}

// ---------------------------------------------------------------------------
// Launch
// ---------------------------------------------------------------------------
extern "C" void kernel_launch(void* const* d_in, const int* in_sizes, int n_in,
                              void* d_out, int out_size) {
    const float* x = (const float*)d_in[0];
    const float* w = (const float*)d_in[1];
    const float* b = (const float*)d_in[2];
    float* out = (float*)d_out;

    void* gwp = nullptr;
    void* gxp = nullptr;
    cudaGetSymbolAddress(&gwp, g_W4);
    cudaGetSymbolAddress(&gxp, g_X4);
    __half* gw = (__half*)gwp;
    __half* gx = (__half*)gxp;

    cudaFuncSetAttribute(gemm_f16_kernel,
                         cudaFuncAttributeMaxDynamicSharedMemorySize, SMEM_TOTAL);

    prep_kernel<<<PREP_GRID, 256>>>(w, gw, (const float4*)x, (uint4*)gx);
    gemm_f16_kernel<<<GRID_M * GRID_N, THREADS, SMEM_TOTAL>>>(gx, gw, b, out);
}

// round 15
// speedup vs baseline: 2.2064x; 1.0005x over previous
#include <cuda_runtime.h>
#include <cuda_fp16.h>
#include <cstdint>
#include <cstddef>

// ============================================================================
// out[8192,4096] = x[8192,4096] @ sym12x12(W)[4096,4096]^T + bias
// R14: fp16 m16n8k16 GEMM, CTA 256x128x64, 4-stage cp.async, 512 threads
//      (16 warps, 4/SMSP), 64x32 warp tiles, single-buffered fragments.
//      FIX vs R13: correct cp.async visibility order at the iteration
//      boundary (wait_group -> __syncthreads -> load_stage). R13's
//      sync->load->wait order let threads read other threads' stage-it
//      data with no happens-before edge -> NaN.
// Prep: fused panel-SMEM W symmetrize+fp16 convert, x fp32->fp16 pack.
// ============================================================================

#define M_DIM 8192
#define N_DIM 4096
#define K_DIM 4096

#define CTA_M 256
#define CTA_N 128
#define CTA_K 64
#define STAGES 4
#define THREADS 512
#define NK_ITERS (K_DIM / CTA_K)          // 64

#define TILE_ROW_BYTES 128                 // 64 fp16 per row
#define A_STAGE_BYTES (CTA_M * TILE_ROW_BYTES)   // 32 KB
#define B_STAGE_BYTES (CTA_N * TILE_ROW_BYTES)   // 16 KB
#define STAGE_BYTES (A_STAGE_BYTES + B_STAGE_BYTES)  // 48 KB
#define SMEM_TOTAL (STAGES * STAGE_BYTES)            // 192 KB

#define GRID_M (M_DIM / CTA_M)             // 32
#define GRID_N (N_DIM / CTA_N)             // 32

// prep grid layout
#define PANW 516                            // 43 12-blocks per panel
#define NPAN 8                              // 8*516 = 4128 >= 4096
#define NSTRIP 341                          // rows 0..4091 symmetrized core
#define NB_W (NSTRIP * NPAN)                // 2728
#define NB_CLEAN 16                         // rows 4092..4095 convert-only
#define NB_X 16384
#define PREP_GRID (NB_W + NB_CLEAN + NB_X)

// Scratch as uint4 arrays for guaranteed 16B alignment (cp.async sources)
__device__ uint4 g_W4[(size_t)N_DIM * (size_t)K_DIM / 8];
__device__ uint4 g_X4[(size_t)M_DIM * (size_t)K_DIM / 8];

// ---------------------------------------------------------------------------
// helpers
// ---------------------------------------------------------------------------
__device__ __forceinline__ uint32_t smem_u32(const void* p) {
    uint32_t a;
    asm("{ .reg .u64 t; cvta.to.shared.u64 t, %1; cvt.u32.u64 %0, t; }" : "=r"(a) : "l"(p));
    return a;
}

#define SWZ(x) ((x) ^ (((x) >> 3) & 0x70))

#define CP_ASYNC16(dst, src) \
    asm volatile("cp.async.cg.shared.global [%0], [%1], 16;" :: "r"(dst), "l"(src) : "memory")
#define CP_ASYNC_COMMIT() asm volatile("cp.async.commit_group;" ::: "memory")
#define CP_ASYNC_WAIT2()  asm volatile("cp.async.wait_group 2;" ::: "memory")

__device__ __forceinline__ void ldsm4(uint32_t* d, uint32_t addr) {
    asm volatile("ldmatrix.sync.aligned.m8n8.x4.shared.b16 {%0,%1,%2,%3}, [%4];"
                 : "=r"(d[0]), "=r"(d[1]), "=r"(d[2]), "=r"(d[3]) : "r"(addr));
}

__device__ __forceinline__ void mma_f16(float* c, const uint32_t* a, const uint32_t* b) {
    asm volatile(
        "mma.sync.aligned.m16n8k16.row.col.f32.f16.f16.f32 "
        "{%0,%1,%2,%3}, {%4,%5,%6,%7}, {%8,%9}, {%0,%1,%2,%3};"
        : "+f"(c[0]), "+f"(c[1]), "+f"(c[2]), "+f"(c[3])
        : "r"(a[0]), "r"(a[1]), "r"(a[2]), "r"(a[3]), "r"(b[0]), "r"(b[1]));
}

// ---------------------------------------------------------------------------
// Fused prep kernel (unchanged from R9/R10)
// ---------------------------------------------------------------------------
__global__ void __launch_bounds__(256)
prep_kernel(const float* __restrict__ W, __half* __restrict__ gw,
            const float4* __restrict__ x, uint4* __restrict__ gx) {
    int bid = blockIdx.x;
    int tid = threadIdx.x;

    if (bid < NB_W) {
        __shared__ float s[12][517];       // 517 % 32 = 5 -> column gather conflict-free
        int strip = bid / NPAN;
        int pan = bid % NPAN;
        int r0 = strip * 12;
        int c0 = pan * PANW;               // multiple of 12
#pragma unroll
        for (int k = 0; k < 25; ++k) {
            int idx = tid + k * 256;
            if (idx < 12 * PANW) {
                int row = idx / PANW, col = idx - row * PANW;
                int cg = c0 + col;
                if (cg < K_DIM)
                    s[row][col] = __ldg(W + (size_t)(r0 + row) * K_DIM + cg);
            }
        }
        __syncthreads();
#pragma unroll
        for (int k = 0; k < 25; ++k) {
            int idx = tid + k * 256;
            if (idx < 12 * PANW) {
                int row = idx / PANW, col = idx - row * PANW;
                int cg = c0 + col;
                if (cg < K_DIM) {
                    float v = s[row][col];
                    if (cg < 4092) {
                        int cm = col % 12;
                        v = 0.5f * (v + s[cm][col - cm + row]);
                    }
                    gw[(size_t)(r0 + row) * K_DIM + cg] = __float2half_rn(v);
                }
            }
        }
    } else if (bid < NB_W + NB_CLEAN) {
        int b = bid - NB_W;
        int base = 4092 * K_DIM + b * 1024 + tid * 4;
#pragma unroll
        for (int j = 0; j < 4; ++j)
            gw[base + j] = __float2half_rn(__ldg(W + base + j));
    } else {
        int i = (bid - NB_W - NB_CLEAN) * 256 + tid;
        float4 v0 = __ldg(x + 2 * i);
        float4 v1 = __ldg(x + 2 * i + 1);
        __half2 h0 = __floats2half2_rn(v0.x, v0.y);
        __half2 h1 = __floats2half2_rn(v0.z, v0.w);
        __half2 h2 = __floats2half2_rn(v1.x, v1.y);
        __half2 h3 = __floats2half2_rn(v1.z, v1.w);
        uint4 u;
        u.x = *reinterpret_cast<uint32_t*>(&h0);
        u.y = *reinterpret_cast<uint32_t*>(&h1);
        u.z = *reinterpret_cast<uint32_t*>(&h2);
        u.w = *reinterpret_cast<uint32_t*>(&h3);
        gx[i] = u;
    }
}

// ---------------------------------------------------------------------------
// GEMM
// ---------------------------------------------------------------------------
__device__ __forceinline__ void load_stage(uint32_t smem_base, int kiter,
                                           const __half* gA, const __half* gB, int tid) {
    int slot = kiter % STAGES;
    uint32_t a_base = smem_base + slot * STAGE_BYTES;
    uint32_t b_base = a_base + A_STAGE_BYTES;
    const __half* gAk = gA + (size_t)kiter * CTA_K;
    const __half* gBk = gB + (size_t)kiter * CTA_K;
    // A: 256 rows x 8 16B-chunks = 2048 -> 4 per thread
#pragma unroll
    for (int i = 0; i < 4; ++i) {
        int c = tid + i * THREADS;
        int row = c >> 3;
        int kc = c & 7;
        uint32_t off = SWZ((uint32_t)(row * TILE_ROW_BYTES + kc * 16));
        CP_ASYNC16(a_base + off, gAk + (size_t)row * K_DIM + kc * 8);
    }
    // B: 128 rows x 8 chunks = 1024 -> 2 per thread
#pragma unroll
    for (int i = 0; i < 2; ++i) {
        int c = tid + i * THREADS;
        int row = c >> 3;
        int kc = c & 7;
        uint32_t off = SWZ((uint32_t)(row * TILE_ROW_BYTES + kc * 16));
        CP_ASYNC16(b_base + off, gBk + (size_t)row * K_DIM + kc * 8);
    }
    CP_ASYNC_COMMIT();
}

__global__ void __launch_bounds__(THREADS, 1)
gemm_f16_kernel(const __half* __restrict__ X, const __half* __restrict__ W,
                const float* __restrict__ bias, float* __restrict__ out) {
    extern __shared__ char smem[];
    uint32_t smem_base = smem_u32(smem);
    int tid = threadIdx.x;
    int wid = tid >> 5;
    int lid = tid & 31;

    // warp grid: 4 (M) x 4 (N); warp tile 64x32
    int warp_m = wid & 3;
    int warp_n = wid >> 2;

    int pid = blockIdx.x;
    const int PPG = 4 * GRID_N;            // 128
    int group = pid / PPG;
    int inpg = pid % PPG;
    int tm = group * 4 + (inpg & 3);
    int tn = inpg >> 2;
    int m0 = tm * CTA_M;
    int n0 = tn * CTA_N;

    const __half* gA = X + (size_t)m0 * K_DIM;
    const __half* gB = W + (size_t)n0 * K_DIM;

    // ---- per-lane ldmatrix row offsets (bytes, pre-swizzle) ----
    int q = lid >> 3;
    int r8 = lid & 7;
    // A x4: [rows0-7,klo][rows8-15,klo][rows0-7,khi][rows8-15,khi]
    int a_row_in = ((q & 1) << 3) + r8;
    int a_gsel = q >> 1;
    uint32_t a_rowb[4];
#pragma unroll
    for (int mt = 0; mt < 4; ++mt)
        a_rowb[mt] = (uint32_t)((warp_m * 64 + mt * 16 + a_row_in) * TILE_ROW_BYTES);
    // B x4: [n8-tile q>>1 within n16 pair, k-granule q&1]
    int b_tile_in = q >> 1;
    int b_gsel = q & 1;
    uint32_t b_rowb[2];                    // 2 n16-pairs cover n32
#pragma unroll
    for (int p = 0; p < 2; ++p)
        b_rowb[p] = (uint32_t)((warp_n * 32 + p * 16 + b_tile_in * 8 + r8) * TILE_ROW_BYTES);

    float acc[4][4][4];                    // [m16 tile][n8 tile][frag]
#pragma unroll
    for (int i = 0; i < 4; ++i)
#pragma unroll
        for (int j = 0; j < 4; ++j)
#pragma unroll
            for (int k = 0; k < 4; ++k) acc[i][j][k] = 0.0f;

    // Prologue: fill 3 stages
#pragma unroll
    for (int j = 0; j < STAGES - 1; ++j) load_stage(smem_base, j, gA, gB, tid);

    uint32_t af[4][4];
    uint32_t bf[2][4];

    for (int it = 0; it < NK_ITERS; ++it) {
        CP_ASYNC_WAIT2();                  // stage `it` landed (3 pending -> <=2), per-thread
        __syncthreads();                   // publish stage `it` block-wide; slot (it-1)%4 free
        if (it + STAGES - 1 < NK_ITERS) load_stage(smem_base, it + STAGES - 1, gA, gB, tid);
        else CP_ASYNC_COMMIT();            // keep group-count invariant exact

        uint32_t a_base = smem_base + (it % STAGES) * STAGE_BYTES;
        uint32_t b_base = a_base + A_STAGE_BYTES;

#pragma unroll
        for (int s = 0; s < 4; ++s) {      // 4 k16-steps cover CTA_K=64
            uint32_t koff = (uint32_t)(s * 32);   // 32B per k16 step
#pragma unroll
            for (int mt = 0; mt < 4; ++mt)
                ldsm4(af[mt], a_base + SWZ(a_rowb[mt] + koff + (uint32_t)(a_gsel * 16)));
#pragma unroll
            for (int p = 0; p < 2; ++p)
                ldsm4(bf[p], b_base + SWZ(b_rowb[p] + koff + (uint32_t)(b_gsel * 16)));
#pragma unroll
            for (int mt = 0; mt < 4; ++mt) {
#pragma unroll
                for (int j = 0; j < 4; ++j)
                    mma_f16(acc[mt][j], af[mt], &bf[j >> 1][2 * (j & 1)]);
            }
        }
    }

    // ---- epilogue: bias + store ----
    int row_base = m0 + warp_m * 64 + (lid >> 2);
    int col_base = n0 + warp_n * 32 + 2 * (lid & 3);
#pragma unroll
    for (int mt = 0; mt < 4; ++mt) {
#pragma unroll
        for (int j = 0; j < 4; ++j) {
            int col = col_base + j * 8;
            float2 b2 = *reinterpret_cast<const float2*>(bias + col);
            int row = row_base + mt * 16;
            float2 v0, v1;
            v0.x = acc[mt][j][0] + b2.x;
            v0.y = acc[mt][j][1] + b2.y;
            v1.x = acc[mt][j][2] + b2.x;
            v1.y = acc[mt][j][3] + b2.y;
            *reinterpret_cast<float2*>(out + (size_t)row * N_DIM + col) = v0;
            *reinterpret_cast<float2*>(out + (size_t)(row + 8) * N_DIM + col) = v1;
        }
    }
}

// ---------------------------------------------------------------------------
// Launch
// ---------------------------------------------------------------------------
extern "C" void kernel_launch(void* const* d_in, const int* in_sizes, int n_in,
                              void* d_out, int out_size) {
    const float* x = (const float*)d_in[0];
    const float* w = (const float*)d_in[1];
    const float* b = (const float*)d_in[2];
    float* out = (float*)d_out;

    void* gwp = nullptr;
    void* gxp = nullptr;
    cudaGetSymbolAddress(&gwp, g_W4);
    cudaGetSymbolAddress(&gxp, g_X4);
    __half* gw = (__half*)gwp;
    __half* gx = (__half*)gxp;

    cudaFuncSetAttribute(gemm_f16_kernel,
                         cudaFuncAttributeMaxDynamicSharedMemorySize, SMEM_TOTAL);

    prep_kernel<<<PREP_GRID, 256>>>(w, gw, (const float4*)x, (uint4*)gx);
    gemm_f16_kernel<<<GRID_M * GRID_N, THREADS, SMEM_TOTAL>>>(gx, gw, b, out);
}